// round 11
// baseline (speedup 1.0000x reference)
#include <cuda_runtime.h>
#include <cuda_fp16.h>
#include <cstdint>

#define N_NODES 50000
#define IN_CH 256
#define OUT_CH 128
#define N_EDGES 800000
#define ELLW 48

typedef unsigned long long u64;
typedef unsigned int u32;

// ---------------- scratch (static device globals; no allocation) ----------------
// g_sg layout: per node, 32 chunks of 16B; chunk j = {s[4j..4j+3], g[4j..4j+3]} fp16.
__device__ half2    g_sg[(size_t)N_NODES * 128];
__device__ u32      g_wt[256 * 256];               // combined [W|Wg]^T, tf32-rounded, [n][k]
__device__ unsigned g_cnt[N_NODES];                // row degree (also ELL cursor)
__device__ int2     g_ell[(size_t)N_NODES * ELLW]; // (col, val-as-int), row-major stride 48
__device__ int      g_idx64_flag;

__device__ __forceinline__ u32 f2tf32(float f) {
    u32 r; asm("cvt.rna.tf32.f32 %0, %1;" : "=r"(r) : "f"(f)); return r;
}

// ---------------- init: zero g_cnt + weight prep + dtype detection ----------------
__global__ __launch_bounds__(256) void initw_kernel(const void* rows, const void* cols,
                                                    const float* __restrict__ W,
                                                    const float* __restrict__ Wg) {
    int i = blockIdx.x * blockDim.x + threadIdx.x;   // 0..65535
    if (i < N_NODES) g_cnt[i] = 0u;
    {
        int n = i >> 8;
        int k = i & 255;
        float v = (n < 128) ? W[(size_t)k * OUT_CH + n] : Wg[(size_t)k * OUT_CH + (n - 128)];
        g_wt[(size_t)n * 256 + k] = f2tf32(v);
    }
    if (i == 0) {
        const long long* r64 = (const long long*)rows;
        const long long* c64 = (const long long*)cols;
        int ok = 1;
        for (int j = 0; j < 16; j++) {
            long long a = r64[j], b = c64[j];
            if (a < 0 || a >= N_NODES) ok = 0;
            if (b < 0 || b >= N_NODES) ok = 0;
        }
        g_idx64_flag = ok;
    }
}

// ---------------- single-pass ELL build: convert + count + place ------------------
__global__ __launch_bounds__(256) void fill_kernel(const void* rows, const void* cols,
                                                   const float* __restrict__ vals) {
    int i = blockIdx.x * blockDim.x + threadIdx.x;
    if (i >= N_EDGES) return;
    int r, c;
    if (g_idx64_flag) {
        r = (int)((const long long*)rows)[i];
        c = (int)((const long long*)cols)[i];
    } else {
        r = ((const int*)rows)[i];
        c = ((const int*)cols)[i];
    }
    float v = vals[i];
    u32 pos = atomicAdd(&g_cnt[r], 1u);
    if (pos < ELLW)
        g_ell[(size_t)r * ELLW + pos] = make_int2(c, __float_as_int(v));
}

// ---------------- mma.sync tf32 dual GEMM (R8 structure: direct ld->smem) ---------
#define KC 16
#define AST 20
#define BST 20

__device__ __forceinline__ void mma_tf32(float c[4], const u32 a[4], const u32 b[2]) {
    asm volatile(
        "mma.sync.aligned.m16n8k8.row.col.f32.tf32.tf32.f32 "
        "{%0,%1,%2,%3}, {%4,%5,%6,%7}, {%8,%9}, {%0,%1,%2,%3};"
        : "+f"(c[0]), "+f"(c[1]), "+f"(c[2]), "+f"(c[3])
        : "r"(a[0]), "r"(a[1]), "r"(a[2]), "r"(a[3]), "r"(b[0]), "r"(b[1]));
}

__global__ __launch_bounds__(512) void gemm_kernel(const float* __restrict__ x) {
    __shared__ u32 As[128 * AST];
    __shared__ u32 Bs[256 * BST];

    const int tid    = threadIdx.x;
    const int wid    = tid >> 5;
    const int lane   = tid & 31;
    const int gid    = lane >> 2;
    const int tig    = lane & 3;
    const int warp_m = wid & 3;
    const int warp_n = wid >> 2;
    const int row0   = blockIdx.x * 128;

    float c[2][8][4];
#pragma unroll
    for (int mt = 0; mt < 2; mt++)
#pragma unroll
        for (int nt = 0; nt < 8; nt++)
#pragma unroll
            for (int q = 0; q < 4; q++) c[mt][nt][q] = 0.f;

    for (int k0 = 0; k0 < IN_CH; k0 += KC) {
        __syncthreads();
        {
            int m  = tid >> 2;
            int kk = (tid & 3) << 2;
            int gr = row0 + m;
            uint4 v = make_uint4(0u, 0u, 0u, 0u);
            if (gr < N_NODES) {
                float4 xv = *(const float4*)&x[(size_t)gr * IN_CH + k0 + kk];
                v.x = f2tf32(xv.x); v.y = f2tf32(xv.y);
                v.z = f2tf32(xv.z); v.w = f2tf32(xv.w);
            }
            *(uint4*)&As[m * AST + kk] = v;
        }
#pragma unroll
        for (int j = 0; j < 2; j++) {
            int e  = tid + j * 512;
            int n  = e >> 2;
            int kk = (e & 3) << 2;
            *(uint4*)&Bs[n * BST + kk] = *(const uint4*)&g_wt[(size_t)n * 256 + k0 + kk];
        }
        __syncthreads();

#pragma unroll
        for (int ks = 0; ks < KC / 8; ks++) {
            const int k = ks * 8;
            u32 a[2][4];
#pragma unroll
            for (int mt = 0; mt < 2; mt++) {
                const int m = warp_m * 32 + mt * 16;
                a[mt][0] = As[(m + gid) * AST + k + tig];
                a[mt][1] = As[(m + gid + 8) * AST + k + tig];
                a[mt][2] = As[(m + gid) * AST + k + tig + 4];
                a[mt][3] = As[(m + gid + 8) * AST + k + tig + 4];
            }
#pragma unroll
            for (int nt = 0; nt < 8; nt++) {
                const int n = warp_n * 64 + nt * 8;
                u32 b[2];
                b[0] = Bs[(n + gid) * BST + k + tig];
                b[1] = Bs[(n + gid) * BST + k + tig + 4];
                mma_tf32(c[0][nt], a[0], b);
                mma_tf32(c[1][nt], a[1], b);
            }
        }
    }

    // epilogue: write fp16 pairs into interleaved g_sg
#pragma unroll
    for (int mt = 0; mt < 2; mt++) {
        const int m = row0 + warp_m * 32 + mt * 16 + gid;
#pragma unroll
        for (int nt = 0; nt < 8; nt++) {
            const int n  = warp_n * 64 + nt * 8 + 2 * tig;
            const int isg = (n >= 128) ? 2 : 0;
            const int nc  = n & 127;
            const int idx = (nc >> 2) * 4 + isg + ((nc & 2) >> 1);
            if (m < N_NODES)
                g_sg[(size_t)m * 128 + idx] =
                    __floats2half2_rn(c[mt][nt][0], c[mt][nt][1]);
            if (m + 8 < N_NODES)
                g_sg[(size_t)(m + 8) * 128 + idx] =
                    __floats2half2_rn(c[mt][nt][2], c[mt][nt][3]);
        }
    }
}

// ---------------- fused ELL SpMM + sigmoid gate: TWO warps per row ----------------
// Warp half h owns slots h, h+2, ... (static addresses -> ev loads issue
// concurrently with the cnt load). Bounded batches: 8, then 4, then scalar tail.
__device__ __forceinline__ void sg_fma(float4& aS, float4& aG, uint4 L, float v) {
    float2 s01 = __half22float2(*(half2*)&L.x);
    float2 s23 = __half22float2(*(half2*)&L.y);
    float2 g01 = __half22float2(*(half2*)&L.z);
    float2 g23 = __half22float2(*(half2*)&L.w);
    aS.x += v * s01.x; aS.y += v * s01.y;
    aS.z += v * s23.x; aS.w += v * s23.y;
    aG.x += v * g01.x; aG.y += v * g01.y;
    aG.z += v * g23.x; aG.w += v * g23.y;
}

__global__ __launch_bounds__(256) void spmm_kernel(float* __restrict__ out) {
    __shared__ float4 red[4][2][32];   // [row-in-block][S/G][lane]

    const int wid   = threadIdx.x >> 5;
    const int lane  = threadIdx.x & 31;
    const int rloc  = wid >> 1;        // 0..3
    const int h     = wid & 1;
    const int row   = blockIdx.x * 4 + rloc;   // 12500*4 = 50000 exactly

    const int2* const base = &g_ell[(size_t)row * ELLW];
    const u32 coff = lane * 4;

    int len = (int)__ldg(&g_cnt[row]);          // issues concurrently with ev batch
    int2 ev[8];
#pragma unroll
    for (int q = 0; q < 8; q++) ev[q] = __ldg(&base[h + 2 * q]);

    len = min(len, ELLW);
    const int mine = max(0, (len - h + 1) >> 1);
    int nq = min(8, mine);

    float4 aS = make_float4(0.f, 0.f, 0.f, 0.f);
    float4 aG = make_float4(0.f, 0.f, 0.f, 0.f);

    {
        uint4 L[8];
#pragma unroll
        for (int q = 0; q < 8; q++)
            if (q < nq) L[q] = *(const uint4*)&g_sg[(size_t)ev[q].x * 128 + coff];
#pragma unroll
        for (int q = 0; q < 8; q++)
            if (q < nq) sg_fma(aS, aG, L[q], __int_as_float(ev[q].y));
    }

    if (mine > 8) {
        const int nq2 = min(4, mine - 8);
        int2 ev2[4];
#pragma unroll
        for (int q = 0; q < 4; q++) ev2[q] = __ldg(&base[h + 16 + 2 * q]);
        uint4 L2[4];
#pragma unroll
        for (int q = 0; q < 4; q++)
            if (q < nq2) L2[q] = *(const uint4*)&g_sg[(size_t)ev2[q].x * 128 + coff];
#pragma unroll
        for (int q = 0; q < 4; q++)
            if (q < nq2) sg_fma(aS, aG, L2[q], __int_as_float(ev2[q].y));
        for (int s = 24 + h; s < len; s += 2) {
            int2 e2 = __ldg(&base[s]);
            uint4 Lt = *(const uint4*)&g_sg[(size_t)e2.x * 128 + coff];
            sg_fma(aS, aG, Lt, __int_as_float(e2.y));
        }
    }

    if (h) {
        red[rloc][0][lane] = aS;
        red[rloc][1][lane] = aG;
    }
    __syncthreads();
    if (!h) {
        float4 bS = red[rloc][0][lane];
        float4 bG = red[rloc][1][lane];
        aS.x += bS.x; aS.y += bS.y; aS.z += bS.z; aS.w += bS.w;
        aG.x += bG.x; aG.y += bG.y; aG.z += bG.z; aG.w += bG.w;
        float4 o;
        o.x = aS.x / (1.f + __expf(-aG.x));
        o.y = aS.y / (1.f + __expf(-aG.y));
        o.z = aS.z / (1.f + __expf(-aG.z));
        o.w = aS.w / (1.f + __expf(-aG.w));
        *(float4*)&out[(size_t)row * OUT_CH + coff] = o;
    }
}

// ---------------- launch: fork ELL branch || GEMM branch, join before spmm --------
extern "C" void kernel_launch(void* const* d_in, const int* in_sizes, int n_in,
                              void* d_out, int out_size) {
    const float* x     = (const float*)d_in[0];
    const void*  erows = d_in[1];
    const void*  ecols = d_in[2];
    const float* evals = (const float*)d_in[3];
    const float* W     = (const float*)d_in[4];
    const float* Wg    = (const float*)d_in[5];
    float* out = (float*)d_out;

    static cudaStream_t s2 = nullptr;
    static cudaEvent_t  ev_fork = nullptr, ev_join = nullptr;
    if (s2 == nullptr) {
        cudaStreamCreateWithFlags(&s2, cudaStreamNonBlocking);
        cudaEventCreateWithFlags(&ev_fork, cudaEventDisableTiming);
        cudaEventCreateWithFlags(&ev_join, cudaEventDisableTiming);
    }

    // shared root: zero cnt + weight prep + dtype detect
    initw_kernel<<<256, 256>>>(erows, ecols, W, Wg);

    // fork: GEMM branch on s2
    cudaEventRecord(ev_fork, 0);
    cudaStreamWaitEvent(s2, ev_fork, 0);
    gemm_kernel<<<(N_NODES + 127) / 128, 512, 0, s2>>>(x);
    cudaEventRecord(ev_join, s2);

    // ELL build on the main stream (single pass)
    fill_kernel<<<(N_EDGES + 255) / 256, 256>>>(erows, ecols, evals);

    // join + spmm
    cudaStreamWaitEvent(0, ev_join, 0);
    spmm_kernel<<<N_NODES / 4, 256>>>(out);
}

// round 17
// speedup vs baseline: 1.0315x; 1.0315x over previous
#include <cuda_runtime.h>
#include <cuda_fp16.h>
#include <cstdint>

#define N_NODES 50000
#define IN_CH 256
#define OUT_CH 128
#define N_EDGES 800000

typedef unsigned long long u64;
typedef unsigned int u32;

#define SCAN_BLOCKS 196        // 196*256 = 50176 >= 50000

// ---------------- scratch (static device globals; no allocation) ----------------
// g_sg layout: per node, 32 chunks of 16B; chunk j = {s[4j..4j+3], g[4j..4j+3]} fp16.
__device__ half2    g_sg[(size_t)N_NODES * 128];
__device__ u32      g_wt[256 * 256];               // combined [W|Wg]^T, tf32-rounded, [n][k]
__device__ int      g_rows[N_EDGES];
__device__ int      g_cols[N_EDGES];
__device__ unsigned g_cnt[N_NODES];
__device__ unsigned g_scan[SCAN_BLOCKS * 256];     // block-local exclusive scans
__device__ unsigned g_bsum[SCAN_BLOCKS];           // per-block totals
__device__ unsigned g_boff[SCAN_BLOCKS];           // per-block exclusive offsets
__device__ int2     g_rowinfo[N_NODES];            // (start, len) packed
__device__ unsigned g_cursor[N_NODES];
__device__ int2     g_csr[N_EDGES];                // (col, val-as-int) in CSR order
__device__ int      g_idx64_flag;

__device__ __forceinline__ u32 f2tf32(float f) {
    u32 r; asm("cvt.rna.tf32.f32 %0, %1;" : "=r"(r) : "f"(f)); return r;
}

// ---------------- init: zero g_cnt + weight prep + dtype detection ----------------
__global__ __launch_bounds__(256) void initw_kernel(const void* rows, const void* cols,
                                                    const float* __restrict__ W,
                                                    const float* __restrict__ Wg) {
    int i = blockIdx.x * blockDim.x + threadIdx.x;   // 0..65535
    if (i < N_NODES) g_cnt[i] = 0u;
    {
        int n = i >> 8;
        int k = i & 255;
        float v = (n < 128) ? W[(size_t)k * OUT_CH + n] : Wg[(size_t)k * OUT_CH + (n - 128)];
        g_wt[(size_t)n * 256 + k] = f2tf32(v);
    }
    if (i == 0) {
        const long long* r64 = (const long long*)rows;
        const long long* c64 = (const long long*)cols;
        int ok = 1;
        for (int j = 0; j < 16; j++) {
            long long a = r64[j], b = c64[j];
            if (a < 0 || a >= N_NODES) ok = 0;
            if (b < 0 || b >= N_NODES) ok = 0;
        }
        g_idx64_flag = ok;
    }
}

__global__ __launch_bounds__(256) void count_kernel(const void* rows, const void* cols) {
    int i = blockIdx.x * blockDim.x + threadIdx.x;
    if (i >= N_EDGES) return;
    int r, c;
    if (g_idx64_flag) {
        r = (int)((const long long*)rows)[i];
        c = (int)((const long long*)cols)[i];
    } else {
        r = ((const int*)rows)[i];
        c = ((const int*)cols)[i];
    }
    g_rows[i] = r;
    g_cols[i] = c;
    atomicAdd(&g_cnt[r], 1u);
}

// ---------------- 3-phase full-chip scan -----------------------------------------
__global__ __launch_bounds__(256) void scan1_kernel() {
    __shared__ unsigned sm[256];
    const int t = threadIdx.x;
    const int i = blockIdx.x * 256 + t;
    unsigned v = (i < N_NODES) ? g_cnt[i] : 0u;
    sm[t] = v;
    __syncthreads();
#pragma unroll
    for (int off = 1; off < 256; off <<= 1) {
        unsigned u = (t >= off) ? sm[t - off] : 0u;
        __syncthreads();
        sm[t] += u;
        __syncthreads();
    }
    g_scan[blockIdx.x * 256 + t] = sm[t] - v;     // exclusive
    if (t == 255) g_bsum[blockIdx.x] = sm[255];
}

__global__ __launch_bounds__(256) void scan2_kernel() {
    __shared__ unsigned sm[256];
    const int t = threadIdx.x;
    unsigned v = (t < SCAN_BLOCKS) ? g_bsum[t] : 0u;
    sm[t] = v;
    __syncthreads();
#pragma unroll
    for (int off = 1; off < 256; off <<= 1) {
        unsigned u = (t >= off) ? sm[t - off] : 0u;
        __syncthreads();
        sm[t] += u;
        __syncthreads();
    }
    if (t < SCAN_BLOCKS) g_boff[t] = sm[t] - v;
}

__global__ __launch_bounds__(256) void scan3_kernel() {
    const int i = blockIdx.x * 256 + threadIdx.x;
    if (i >= N_NODES) return;
    unsigned r = g_boff[blockIdx.x] + g_scan[i];
    g_rowinfo[i] = make_int2((int)r, (int)g_cnt[i]);
    g_cursor[i]  = r;
}

__global__ __launch_bounds__(256) void fill_kernel(const float* __restrict__ vals) {
    int i = blockIdx.x * blockDim.x + threadIdx.x;
    if (i >= N_EDGES) return;
    int r = g_rows[i];
    unsigned pos = atomicAdd(&g_cursor[r], 1u);
    if (pos < (unsigned)N_EDGES)
        g_csr[pos] = make_int2(g_cols[i], __float_as_int(vals[i]));
}

// ---------------- mma.sync tf32 dual GEMM, fp16 interleaved epilogue --------------
#define KC 16
#define AST 20
#define BST 20

__device__ __forceinline__ void mma_tf32(float c[4], const u32 a[4], const u32 b[2]) {
    asm volatile(
        "mma.sync.aligned.m16n8k8.row.col.f32.tf32.tf32.f32 "
        "{%0,%1,%2,%3}, {%4,%5,%6,%7}, {%8,%9}, {%0,%1,%2,%3};"
        : "+f"(c[0]), "+f"(c[1]), "+f"(c[2]), "+f"(c[3])
        : "r"(a[0]), "r"(a[1]), "r"(a[2]), "r"(a[3]), "r"(b[0]), "r"(b[1]));
}

__global__ __launch_bounds__(512) void gemm_kernel(const float* __restrict__ x) {
    __shared__ u32 As[128 * AST];
    __shared__ u32 Bs[256 * BST];

    const int tid    = threadIdx.x;
    const int wid    = tid >> 5;
    const int lane   = tid & 31;
    const int gid    = lane >> 2;
    const int tig    = lane & 3;
    const int warp_m = wid & 3;
    const int warp_n = wid >> 2;
    const int row0   = blockIdx.x * 128;

    float c[2][8][4];
#pragma unroll
    for (int mt = 0; mt < 2; mt++)
#pragma unroll
        for (int nt = 0; nt < 8; nt++)
#pragma unroll
            for (int q = 0; q < 4; q++) c[mt][nt][q] = 0.f;

    for (int k0 = 0; k0 < IN_CH; k0 += KC) {
        __syncthreads();
        {
            int m  = tid >> 2;
            int kk = (tid & 3) << 2;
            int gr = row0 + m;
            uint4 v = make_uint4(0u, 0u, 0u, 0u);
            if (gr < N_NODES) {
                float4 xv = *(const float4*)&x[(size_t)gr * IN_CH + k0 + kk];
                v.x = f2tf32(xv.x); v.y = f2tf32(xv.y);
                v.z = f2tf32(xv.z); v.w = f2tf32(xv.w);
            }
            *(uint4*)&As[m * AST + kk] = v;
        }
#pragma unroll
        for (int j = 0; j < 2; j++) {
            int e  = tid + j * 512;
            int n  = e >> 2;
            int kk = (e & 3) << 2;
            *(uint4*)&Bs[n * BST + kk] = *(const uint4*)&g_wt[(size_t)n * 256 + k0 + kk];
        }
        __syncthreads();

#pragma unroll
        for (int ks = 0; ks < KC / 8; ks++) {
            const int k = ks * 8;
            u32 a[2][4];
#pragma unroll
            for (int mt = 0; mt < 2; mt++) {
                const int m = warp_m * 32 + mt * 16;
                a[mt][0] = As[(m + gid) * AST + k + tig];
                a[mt][1] = As[(m + gid + 8) * AST + k + tig];
                a[mt][2] = As[(m + gid) * AST + k + tig + 4];
                a[mt][3] = As[(m + gid + 8) * AST + k + tig + 4];
            }
#pragma unroll
            for (int nt = 0; nt < 8; nt++) {
                const int n = warp_n * 64 + nt * 8;
                u32 b[2];
                b[0] = Bs[(n + gid) * BST + k + tig];
                b[1] = Bs[(n + gid) * BST + k + tig + 4];
                mma_tf32(c[0][nt], a[0], b);
                mma_tf32(c[1][nt], a[1], b);
            }
        }
    }

    // epilogue: write fp16 pairs into interleaved g_sg
#pragma unroll
    for (int mt = 0; mt < 2; mt++) {
        const int m = row0 + warp_m * 32 + mt * 16 + gid;
#pragma unroll
        for (int nt = 0; nt < 8; nt++) {
            const int n  = warp_n * 64 + nt * 8 + 2 * tig;
            const int isg = (n >= 128) ? 2 : 0;
            const int nc  = n & 127;
            const int idx = (nc >> 2) * 4 + isg + ((nc & 2) >> 1);
            if (m < N_NODES)
                g_sg[(size_t)m * 128 + idx] =
                    __floats2half2_rn(c[mt][nt][0], c[mt][nt][1]);
            if (m + 8 < N_NODES)
                g_sg[(size_t)(m + 8) * 128 + idx] =
                    __floats2half2_rn(c[mt][nt][2], c[mt][nt][3]);
        }
    }
}

// ---------------- fused CSR SpMM + sigmoid gate: ONE warp per row, no barriers ----
__device__ __forceinline__ void sg_fma(float4& aS, float4& aG, uint4 L, float v) {
    float2 s01 = __half22float2(*(half2*)&L.x);
    float2 s23 = __half22float2(*(half2*)&L.y);
    float2 g01 = __half22float2(*(half2*)&L.z);
    float2 g23 = __half22float2(*(half2*)&L.w);
    aS.x += v * s01.x; aS.y += v * s01.y;
    aS.z += v * s23.x; aS.w += v * s23.y;
    aG.x += v * g01.x; aG.y += v * g01.y;
    aG.z += v * g23.x; aG.w += v * g23.y;
}

__global__ __launch_bounds__(256) void spmm_kernel(float* __restrict__ out) {
    const int row  = (blockIdx.x * blockDim.x + threadIdx.x) >> 5;
    const int lane = threadIdx.x & 31;
    if (row >= N_NODES) return;
    const u32 coff = lane * 4;

    const int2 info = __ldg(&g_rowinfo[row]);
    int e = info.x;
    const int end = info.x + info.y;

    float4 aS = make_float4(0.f, 0.f, 0.f, 0.f);
    float4 aG = make_float4(0.f, 0.f, 0.f, 0.f);

    while (e < end) {
        const int rem = end - e;
        int2 ev[8];
#pragma unroll
        for (int q = 0; q < 8; q++)
            ev[q] = (q < rem) ? __ldg(&g_csr[e + q]) : make_int2(0, 0);
        uint4 L[8];
#pragma unroll
        for (int q = 0; q < 8; q++)
            if (q < rem) L[q] = *(const uint4*)&g_sg[(size_t)ev[q].x * 128 + coff];
#pragma unroll
        for (int q = 0; q < 8; q++)
            if (q < rem) sg_fma(aS, aG, L[q], __int_as_float(ev[q].y));
        e += 8;
    }

    float4 o;
    o.x = aS.x / (1.f + __expf(-aG.x));
    o.y = aS.y / (1.f + __expf(-aG.y));
    o.z = aS.z / (1.f + __expf(-aG.z));
    o.w = aS.w / (1.f + __expf(-aG.w));
    *(float4*)&out[(size_t)row * OUT_CH + coff] = o;
}

// ---------------- launch: fork CSR branch || GEMM branch, join before spmm --------
extern "C" void kernel_launch(void* const* d_in, const int* in_sizes, int n_in,
                              void* d_out, int out_size) {
    const float* x     = (const float*)d_in[0];
    const void*  erows = d_in[1];
    const void*  ecols = d_in[2];
    const float* evals = (const float*)d_in[3];
    const float* W     = (const float*)d_in[4];
    const float* Wg    = (const float*)d_in[5];
    float* out = (float*)d_out;

    static cudaStream_t s2 = nullptr;
    static cudaEvent_t  ev_fork = nullptr, ev_join = nullptr;
    if (s2 == nullptr) {
        cudaStreamCreateWithFlags(&s2, cudaStreamNonBlocking);
        cudaEventCreateWithFlags(&ev_fork, cudaEventDisableTiming);
        cudaEventCreateWithFlags(&ev_join, cudaEventDisableTiming);
    }

    // shared root: zero cnt + weight prep + dtype detect
    initw_kernel<<<256, 256>>>(erows, ecols, W, Wg);

    // fork: GEMM branch on s2
    cudaEventRecord(ev_fork, 0);
    cudaStreamWaitEvent(s2, ev_fork, 0);
    gemm_kernel<<<(N_NODES + 127) / 128, 512, 0, s2>>>(x);
    cudaEventRecord(ev_join, s2);

    // CSR branch on the main stream
    count_kernel<<<(N_EDGES + 255) / 256, 256>>>(erows, ecols);
    scan1_kernel<<<SCAN_BLOCKS, 256>>>();
    scan2_kernel<<<1, 256>>>();
    scan3_kernel<<<SCAN_BLOCKS, 256>>>();
    fill_kernel<<<(N_EDGES + 255) / 256, 256>>>(evals);

    // join + spmm (1 warp/row, no barriers)
    cudaStreamWaitEvent(0, ev_join, 0);
    spmm_kernel<<<(N_NODES + 7) / 8, 256>>>(out);
}